// round 6
// baseline (speedup 1.0000x reference)
#include <cuda_runtime.h>
#include <cuda_fp16.h>
#include <cstdint>

// ---------------- problem constants ----------------
#define GGRP   8
#define DDISP  64
#define EDIM   128
#define K1DIM  72            // G*9
#define MTOT   409600        // N*NS
#define TILE_M 128
#define NTILES 3200          // MTOT / TILE_M
#define GRID_X 152
#define NTHR   256           // 8 warps, each owns m16 x n128
#define EMB_ELEMS 52428800   // MTOT*EDIM
#define TOT_ELEMS 52838400   // + MTOT

// ---------------- smem layout ----------------
// A1: u32 words, row stride 44 (bank 12r+kp distinct)   [double buffered]
// B pair layout for LDS.64: pair(kp0=8s+ti, kp0+4) at s*PAIR_S + ti*PAIR_TI + n
//   PAIR_TI=136 -> 2W mod 32 = 16*ti + 2g : conflict-free in both half-warp phases
// REC: per-warp record staging: 4 pixels x 8 groups x 68 floats (pad 64->68)
#define A1_STRIDE 44
#define PAIR_TI   136
#define PAIR_S    544
#define TAB_STRIDE 132
#define REC_G     68
#define REC_WARP_BYTES (4*GGRP*REC_G*4)           // 8704

#define OFF_LABEL 0                               // 2 x 128 ints
#define OFF_BIAS1 1024
#define OFF_BIAS2 1536
#define OFF_B1    2048                            // 5*544*8  = 21760
#define OFF_B2    (OFF_B1 + 5*PAIR_S*8)           // 8*544*8  = 34816
#define OFF_A1    (OFF_B2 + 8*PAIR_S*8)           // 2*128*44*4 = 45056
#define A1_BUF_BYTES (TILE_M*A1_STRIDE*4)
#define OFF_TAB   (OFF_A1 + 2*A1_BUF_BYTES)       // 64*132*4 = 33792
#define OFF_REC   (OFF_TAB + DDISP*TAB_STRIDE*4)  // 8*8704   = 69632
#define SMEM_TOTAL (OFF_REC + 8*REC_WARP_BYTES)   // 207104 B

// prologue staging (reused regions):
#define W2S_STRIDE 68
#define WPT_STRIDE 66

// ---------------- helpers ----------------
__device__ __forceinline__ void mma_f16(float c[4], uint32_t a0, uint32_t a1,
                                        uint32_t a2, uint32_t a3,
                                        uint32_t b0, uint32_t b1) {
    asm volatile(
        "mma.sync.aligned.m16n8k16.row.col.f32.f16.f16.f32 "
        "{%0,%1,%2,%3}, {%4,%5,%6,%7}, {%8,%9}, {%0,%1,%2,%3};"
        : "+f"(c[0]), "+f"(c[1]), "+f"(c[2]), "+f"(c[3])
        : "r"(a0), "r"(a1), "r"(a2), "r"(a3), "r"(b0), "r"(b1));
}

__device__ __forceinline__ float gelu_fast(float x) {
    float p = x * fmaf(x * x, 0.0713548163f, 1.5957691216f);
    float e;
    asm("ex2.approx.ftz.f32 %0, %1;" : "=f"(e) : "f"(-1.4426950408889634f * p));
    float r;
    asm("rcp.approx.ftz.f32 %0, %1;" : "=f"(r) : "f"(1.0f + e));
    return x * r;
}

__device__ __forceinline__ uint32_t pack_h2(float lo, float hi) {
    __half2 h = __floats2half2_rn(lo, hi);
    return *(uint32_t*)&h;
}

__device__ __forceinline__ uint32_t smem_u32(const void* p) {
    uint32_t a;
    asm("{ .reg .u64 t; cvta.to.shared.u64 t, %1; cvt.u32.u64 %0, t; }" : "=r"(a) : "l"(p));
    return a;
}

#define CP_ASYNC16(dst, src) \
    asm volatile("cp.async.cg.shared.global [%0], [%1], 16;" :: "r"(dst), "l"(src))
#define CP_COMMIT()  asm volatile("cp.async.commit_group;")
#define CP_WAIT0()   asm volatile("cp.async.wait_group 0;")

// half index in B pair layout for element (k, n)
__device__ __forceinline__ int pair_half_idx(int k, int n) {
    int kp = k >> 1, h = k & 1;
    int s = kp >> 3, rem = kp & 7;
    int ti = rem & 3, w = rem >> 2;
    return ((s * PAIR_S + ti * PAIR_TI + n) * 2 + w) * 2 + h;
}

// ---------------- single fused kernel ----------------
__global__ void __launch_bounds__(NTHR, 1)
propagation_kernel(const float* __restrict__ cost, const int* __restrict__ label,
                   const float* __restrict__ W1, const float* __restrict__ b1,
                   const float* __restrict__ W2, const float* __restrict__ b2,
                   const float* __restrict__ Wp,
                   float* __restrict__ out_embed, float* __restrict__ out_label) {
    extern __shared__ char smem[];
    const int tid = threadIdx.x;
    const int wid = tid >> 5, lid = tid & 31;
    const int g = lid >> 2, ti = lid & 3;     // mma fragment coords
    const int mbase = wid * 16;               // warp owns rows [mbase, mbase+16)
    const int grow = mbase + (lid >> 1);      // extraction row for this thread
    const int grp4 = (lid & 1) * 4;           // extraction group base
    const int prow = lid >> 3;                // extraction local pixel (0..3)

    int*      labels_s = (int*)(smem + OFF_LABEL);
    float*    b1s   = (float*)(smem + OFF_BIAS1);
    float*    b2ps  = (float*)(smem + OFF_BIAS2);
    uint2*    B1p   = (uint2*)(smem + OFF_B1);
    uint2*    B2p   = (uint2*)(smem + OFF_B2);
    __half*   B1h   = (__half*)(smem + OFF_B1);
    __half*   B2h   = (__half*)(smem + OFF_B2);
    uint32_t* A1u   = (uint32_t*)(smem + OFF_A1);
    float*    tabs  = (float*)(smem + OFF_TAB);
    float*    recw  = (float*)(smem + OFF_REC + wid * REC_WARP_BYTES);
    const uint32_t rec_sa = smem_u32(recw);

    // ================= PROLOGUE =================
    {
        __half* W2sh  = (__half*)(smem + OFF_A1);
        __half* WpTsh = (__half*)(smem + OFF_TAB);
        for (int idx = tid; idx < EDIM * EDIM; idx += NTHR) {
            int r = idx >> 7, j = idx & 127;
            W2sh[(r * W2S_STRIDE + (j >> 1)) * 2 + (j & 1)] = __float2half(__ldg(W2 + idx));
            int jj = idx >> 7, n = idx & 127;
            WpTsh[(n * WPT_STRIDE + (jj >> 1)) * 2 + (jj & 1)] = __float2half(__ldg(Wp + idx));
        }
        for (int idx = tid; idx < K1DIM * EDIM; idx += NTHR) {
            int k = idx >> 7, n = idx & 127;
            B1h[pair_half_idx(k, n)] = __float2half(__ldg(W1 + idx));
        }
        // zero B1 pad words (kp 36..39): s=4, w=1
        for (int i = tid; i < 512; i += NTHR) {
            int t4 = i >> 7, n = i & 127;
            ((uint32_t*)B1p)[(4 * PAIR_S + t4 * PAIR_TI + n) * 2 + 1] = 0;
        }
        if (tid < EDIM) b1s[tid] = __ldg(b1 + tid);
    }
    __syncthreads();

    // --- fold W2p = W2 @ Wp_top with tensor cores ---
    {
        const uint32_t* W2s  = (const uint32_t*)(smem + OFF_A1);
        const uint32_t* WpTs = (const uint32_t*)(smem + OFF_TAB);
        float facc[16][4];
        #pragma unroll
        for (int j = 0; j < 16; j++)
            #pragma unroll
            for (int u = 0; u < 4; u++) facc[j][u] = 0.f;
        #pragma unroll
        for (int s = 0; s < 8; s++) {
            int jp0 = 8 * s + ti;
            uint32_t a0 = W2s[(mbase + g) * W2S_STRIDE + jp0];
            uint32_t a1 = W2s[(mbase + g + 8) * W2S_STRIDE + jp0];
            uint32_t a2 = W2s[(mbase + g) * W2S_STRIDE + jp0 + 4];
            uint32_t a3 = W2s[(mbase + g + 8) * W2S_STRIDE + jp0 + 4];
            #pragma unroll
            for (int j = 0; j < 16; j++) {
                uint32_t b0 = WpTs[(8 * j + g) * WPT_STRIDE + jp0];
                uint32_t b1v = WpTs[(8 * j + g) * WPT_STRIDE + jp0 + 4];
                mma_f16(facc[j], a0, a1, a2, a3, b0, b1v);
            }
        }
        #pragma unroll
        for (int j = 0; j < 16; j++) {
            int n0 = 8 * j + 2 * ti;
            B2h[pair_half_idx(mbase + g, n0)]     = __float2half(facc[j][0]);
            B2h[pair_half_idx(mbase + g, n0 + 1)] = __float2half(facc[j][1]);
            B2h[pair_half_idx(mbase + g + 8, n0)]     = __float2half(facc[j][2]);
            B2h[pair_half_idx(mbase + g + 8, n0 + 1)] = __float2half(facc[j][3]);
        }
        if (tid < EDIM) {
            float ba = 0.f;
            #pragma unroll 8
            for (int j = 0; j < EDIM; j++) ba += __ldg(b2 + j) * __ldg(Wp + (size_t)j * EDIM + tid);
            b2ps[tid] = ba;
        }
    }
    __syncthreads();

    // --- fourier scratch in A1 region ---
    {
        float* scr = (float*)(smem + OFF_A1);
        for (int t = tid; t < 960; t += NTHR) {
            int d = t / 15, i = t - d * 15;
            float coordf = (float)d * (float)(3.14 / 64.0);
            float fr = coordf * (float)(1 << i);
            scr[d * 32 + i]      = (float)sin((double)fr);
            scr[d * 32 + 15 + i] = (float)cos((double)fr);
            if (i == 0) scr[d * 32 + 30] = coordf;
        }
    }
    __syncthreads();

    // --- table[d][n] = bias2p[n] + fourier(d) @ Wp_bot ---
    {
        const float* scr = (const float*)(smem + OFF_A1);
        int n = tid & 127, dh = tid >> 7;
        float wpc[31];
        #pragma unroll
        for (int c = 0; c < 31; c++) wpc[c] = __ldg(Wp + (size_t)(EDIM + c) * EDIM + n);
        float bb = b2ps[n];
        #pragma unroll 4
        for (int u = 0; u < 32; u++) {
            int d = dh + 2 * u;
            float acc = bb;
            #pragma unroll
            for (int c = 0; c < 31; c++) acc += scr[d * 32 + c] * wpc[c];
            tabs[d * TAB_STRIDE + n] = acc;
        }
    }
    __syncthreads();

    // --- zero A1 K-pad words (kp 36..39), both buffers ---
    uint32_t* A1w0 = A1u + mbase * A1_STRIDE;
    uint32_t* A1w1 = A1u + (A1_BUF_BYTES / 4) + mbase * A1_STRIDE;
    for (int i = lid; i < 64; i += 32) {
        A1w0[(i >> 2) * A1_STRIDE + 36 + (i & 3)] = 0;
        A1w1[(i >> 2) * A1_STRIDE + 36 + (i & 3)] = 0;
    }

    uint32_t* Gdst0 = A1w0 + (lid >> 1) * A1_STRIDE + (lid & 1) * 18;
    uint32_t* Gdst1 = A1w1 + (lid >> 1) * A1_STRIDE + (lid & 1) * 18;

    // --- first tile: coalesced record stage + extract into buffer 0 ---
    {
        int t0 = blockIdx.x;
        int pix0 = t0 * (TILE_M / 4) + wid * 4;
        const float* gsrc = cost + (size_t)pix0 * (GGRP * DDISP) + lid * 4;
        #pragma unroll
        for (int u = 0; u < 16; u++) {
            int p = u >> 2, gg = (u & 3) * 2 + (lid >> 4);
            uint32_t dst = rec_sa + (((p * GGRP + gg) * REC_G + (lid & 15) * 4)) * 4;
            CP_ASYNC16(dst, gsrc + u * 128);
        }
        CP_COMMIT();

        int draw = __ldg(label + t0 * TILE_M + grow);
        if ((lid & 1) == 0) {
            labels_s[grow] = draw;
            if (out_label) out_label[t0 * TILE_M + grow] = (float)draw;
        }
        CP_WAIT0();
        __syncwarp();

        int dcl = draw < 0 ? 0 : (draw > 63 ? 63 : draw);
        float gv[36];
        #pragma unroll
        for (int gi = 0; gi < 4; gi++) {
            const float* rs = recw + (prow * GGRP + grp4 + gi) * REC_G;
            #pragma unroll
            for (int c = 0; c < 9; c++) {
                int ix = dcl - 4 + c;
                ix = ix < 0 ? 0 : (ix > 63 ? 63 : ix);
                gv[gi * 9 + c] = rs[ix];
            }
        }
        #pragma unroll
        for (int w = 0; w < 18; w++) Gdst0[w] = pack_h2(gv[2 * w], gv[2 * w + 1]);
    }
    __syncwarp();

    // ================= MAIN LOOP =================
    int cb = 0;
    for (int tile = blockIdx.x; tile < NTILES; tile += GRID_X) {
        const int m0 = tile * TILE_M;
        const int nxt = tile + GRID_X;
        const bool hn = nxt < NTILES;
        uint32_t* A1w = cb ? A1w1 : A1w0;
        uint32_t* Gdst = cb ? Gdst0 : Gdst1;

        int draw = 0;
        if (hn) draw = __ldg(label + nxt * TILE_M + grow);

        // ---- GEMM1: m16 x n128, K=80 (5 k16 steps) ----
        float acc1[16][4];
        #pragma unroll
        for (int j = 0; j < 16; j++)
            #pragma unroll
            for (int u = 0; u < 4; u++) acc1[j][u] = 0.f;

        #pragma unroll
        for (int s = 0; s < 5; s++) {
            int kp0 = 8 * s + ti;
            uint32_t a0 = A1w[g * A1_STRIDE + kp0];
            uint32_t a1 = A1w[(g + 8) * A1_STRIDE + kp0];
            uint32_t a2 = A1w[g * A1_STRIDE + kp0 + 4];
            uint32_t a3 = A1w[(g + 8) * A1_STRIDE + kp0 + 4];
            const uint2* bp = B1p + s * PAIR_S + ti * PAIR_TI + g;
            #pragma unroll
            for (int j = 0; j < 16; j++) {
                uint2 b = bp[8 * j];
                mma_f16(acc1[j], a0, a1, a2, a3, b.x, b.y);
            }
        }

        // ---- gelu(x+b1), repack C-frags as GEMM2 A-frags ----
        uint32_t ha[8][4];
        #pragma unroll
        for (int s = 0; s < 8; s++) {
            int j0 = 2 * s, j1 = 2 * s + 1;
            float2 bb0 = *(const float2*)(b1s + 8 * j0 + 2 * ti);
            float2 bb1 = *(const float2*)(b1s + 8 * j1 + 2 * ti);
            ha[s][0] = pack_h2(gelu_fast(acc1[j0][0] + bb0.x), gelu_fast(acc1[j0][1] + bb0.y));
            ha[s][1] = pack_h2(gelu_fast(acc1[j0][2] + bb0.x), gelu_fast(acc1[j0][3] + bb0.y));
            ha[s][2] = pack_h2(gelu_fast(acc1[j1][0] + bb1.x), gelu_fast(acc1[j1][1] + bb1.y));
            ha[s][3] = pack_h2(gelu_fast(acc1[j1][2] + bb1.x), gelu_fast(acc1[j1][3] + bb1.y));
        }

        // ---- issue next-tile coalesced record stage (cp.async, no regs held) ----
        if (hn) {
            int pix0 = nxt * (TILE_M / 4) + wid * 4;
            const float* gsrc = cost + (size_t)pix0 * (GGRP * DDISP) + lid * 4;
            #pragma unroll
            for (int u = 0; u < 16; u++) {
                int p = u >> 2, gg = (u & 3) * 2 + (lid >> 4);
                uint32_t dst = rec_sa + (((p * GGRP + gg) * REC_G + (lid & 15) * 4)) * 4;
                CP_ASYNC16(dst, gsrc + u * 128);
            }
            CP_COMMIT();
        }

        // ---- GEMM2: A from registers, K=128 (8 k16 steps) ----
        float acc2[16][4];
        #pragma unroll
        for (int j = 0; j < 16; j++)
            #pragma unroll
            for (int u = 0; u < 4; u++) acc2[j][u] = 0.f;

        #pragma unroll
        for (int s = 0; s < 8; s++) {
            const uint2* bp = B2p + s * PAIR_S + ti * PAIR_TI + g;
            #pragma unroll
            for (int j = 0; j < 16; j++) {
                uint2 b = bp[8 * j];
                mma_f16(acc2[j], ha[s][0], ha[s][1], ha[s][2], ha[s][3], b.x, b.y);
            }
        }

        // ---- epilogue: out = acc2 + table[d] ----
        {
            int r0 = mbase + g, r1 = r0 + 8;
            int d0 = labels_s[cb * TILE_M + r0];
            int d1 = labels_s[cb * TILE_M + r1];
            d0 = d0 < 0 ? 0 : (d0 > 63 ? 63 : d0);
            d1 = d1 < 0 ? 0 : (d1 > 63 ? 63 : d1);
            const float* t0 = tabs + d0 * TAB_STRIDE + 2 * ti;
            const float* t1 = tabs + d1 * TAB_STRIDE + 2 * ti;
            float* o0 = out_embed + (size_t)(m0 + r0) * EDIM + 2 * ti;
            float* o1 = out_embed + (size_t)(m0 + r1) * EDIM + 2 * ti;
            #pragma unroll
            for (int j = 0; j < 16; j++) {
                float2 tv0 = *(const float2*)(t0 + 8 * j);
                float2 tv1 = *(const float2*)(t1 + 8 * j);
                float2 v0, v1;
                v0.x = acc2[j][0] + tv0.x;  v0.y = acc2[j][1] + tv0.y;
                v1.x = acc2[j][2] + tv1.x;  v1.y = acc2[j][3] + tv1.y;
                *(float2*)(o0 + 8 * j) = v0;
                *(float2*)(o1 + 8 * j) = v1;
            }
        }

        // ---- extract next-tile windows from staged records -> A1[cb^1] ----
        if (hn) {
            CP_WAIT0();
            __syncwarp();
            int dcl = draw < 0 ? 0 : (draw > 63 ? 63 : draw);
            float gv[36];
            #pragma unroll
            for (int gi = 0; gi < 4; gi++) {
                const float* rs = recw + (prow * GGRP + grp4 + gi) * REC_G;
                #pragma unroll
                for (int c = 0; c < 9; c++) {
                    int ix = dcl - 4 + c;
                    ix = ix < 0 ? 0 : (ix > 63 ? 63 : ix);
                    gv[gi * 9 + c] = rs[ix];
                }
            }
            #pragma unroll
            for (int w = 0; w < 18; w++) Gdst[w] = pack_h2(gv[2 * w], gv[2 * w + 1]);
            if ((lid & 1) == 0) {
                labels_s[(cb ^ 1) * TILE_M + grow] = draw;
                if (out_label) out_label[nxt * TILE_M + grow] = (float)draw;
            }
        }
        __syncwarp();
        cb ^= 1;
    }
}

// ---------------- launch ----------------
extern "C" void kernel_launch(void* const* d_in, const int* in_sizes, int n_in,
                              void* d_out, int out_size) {
    const float* cost  = (const float*)d_in[0];
    const int*   label = (const int*)d_in[1];
    // d_in[2] = context (unused: layers=[] passthrough)
    const float* W1 = (const float*)d_in[3];
    const float* b1 = (const float*)d_in[4];
    const float* W2 = (const float*)d_in[5];
    const float* b2 = (const float*)d_in[6];
    const float* Wp = (const float*)d_in[7];

    float* out = (float*)d_out;
    float* out_label = (out_size >= TOT_ELEMS) ? (out + EMB_ELEMS) : nullptr;

    cudaFuncSetAttribute(propagation_kernel,
                         cudaFuncAttributeMaxDynamicSharedMemorySize, SMEM_TOTAL);

    propagation_kernel<<<GRID_X, NTHR, SMEM_TOTAL>>>(cost, label, W1, b1, W2, b2, Wp,
                                                     out, out_label);
}

// round 7
// speedup vs baseline: 1.0273x; 1.0273x over previous
#include <cuda_runtime.h>
#include <cuda_fp16.h>
#include <cstdint>

// ---------------- problem constants ----------------
#define GGRP   8
#define DDISP  64
#define EDIM   128
#define K1DIM  72            // G*9
#define MTOT   409600        // N*NS
#define TILE_M 128
#define NTILES 3200          // MTOT / TILE_M
#define GRID_X 152
#define NTHR   256           // 8 warps, each owns m16 x n128
#define EMB_ELEMS 52428800   // MTOT*EDIM
#define TOT_ELEMS 52838400   // + MTOT

// ---------------- smem layout ----------------
// A1: u32 words, row stride 44 (bank 12r+kp distinct per phase) [double buffered]
// B pair layout for LDS.64: pair(kp0=8s+ti, kp0+4) at s*PAIR_S + ti*PAIR_TI + n
//   PAIR_TI=132 -> per-16-lane phase banks 8ti+2g distinct (conflict-free)
// B2 is AUGMENTED: steps 0..7 = W2@Wp (K=128), steps 8..11 = one-hot table rows
// STG staging: per-warp 16 rows x 128 words, col xor-swizzled by 8*(g&3)
#define A1_STRIDE 44
#define PAIR_TI   132
#define PAIR_S    528
#define NSTEP2    12                              // 8 real + 4 one-hot

#define OFF_LABEL 0                               // 2 x 128 ints
#define OFF_BIAS1 1024
#define OFF_BIAS2 1536                            // temp (prologue only)
#define OFF_B1    2048                            // 5*528*8  = 21120
#define OFF_B2    (OFF_B1 + 5*PAIR_S*8)           // 12*528*8 = 50688
#define OFF_A1    (OFF_B2 + NSTEP2*PAIR_S*8)      // 2*128*44*4 = 45056
#define A1_BUF_BYTES (TILE_M*A1_STRIDE*4)
#define OFF_STG   (OFF_A1 + 2*A1_BUF_BYTES)       // 8 * 8192 = 65536
#define SMEM_TOTAL (OFF_STG + 8*8192)             // 184448 B

// prologue staging (reused regions):
#define W2S_STRIDE 68                             // in A1 region
#define WPT_STRIDE 66                             // in STG region

// ---------------- helpers ----------------
__device__ __forceinline__ void mma_f16(float c[4], uint32_t a0, uint32_t a1,
                                        uint32_t a2, uint32_t a3,
                                        uint32_t b0, uint32_t b1) {
    asm volatile(
        "mma.sync.aligned.m16n8k16.row.col.f32.f16.f16.f32 "
        "{%0,%1,%2,%3}, {%4,%5,%6,%7}, {%8,%9}, {%0,%1,%2,%3};"
        : "+f"(c[0]), "+f"(c[1]), "+f"(c[2]), "+f"(c[3])
        : "r"(a0), "r"(a1), "r"(a2), "r"(a3), "r"(b0), "r"(b1));
}

__device__ __forceinline__ float gelu_fast(float x) {
    float p = x * fmaf(x * x, 0.0713548163f, 1.5957691216f);
    float e;
    asm("ex2.approx.ftz.f32 %0, %1;" : "=f"(e) : "f"(-1.4426950408889634f * p));
    float r;
    asm("rcp.approx.ftz.f32 %0, %1;" : "=f"(r) : "f"(1.0f + e));
    return x * r;
}

__device__ __forceinline__ uint32_t pack_h2(float lo, float hi) {
    __half2 h = __floats2half2_rn(lo, hi);
    return *(uint32_t*)&h;
}

// one-hot half2 word: halves (d==kb, d==kb+1) as f16 1.0
__device__ __forceinline__ uint32_t oh2(int d, int kb) {
    uint32_t r = (d == kb) ? 0x3C00u : 0u;
    if (d == kb + 1) r |= 0x3C000000u;
    return r;
}

// half index in B pair layout for element (k, n), k < 2*8*NSTEP2
__device__ __forceinline__ int pair_half_idx(int k, int n) {
    int kp = k >> 1, h = k & 1;
    int s = kp >> 3, rem = kp & 7;
    int ti = rem & 3, w = rem >> 2;
    return ((s * PAIR_S + ti * PAIR_TI + n) * 2 + w) * 2 + h;
}

// ---------------- single fused kernel ----------------
__global__ void __launch_bounds__(NTHR, 1)
propagation_kernel(const float* __restrict__ cost, const int* __restrict__ label,
                   const float* __restrict__ W1, const float* __restrict__ b1,
                   const float* __restrict__ W2, const float* __restrict__ b2,
                   const float* __restrict__ Wp,
                   float* __restrict__ out_embed, float* __restrict__ out_label) {
    extern __shared__ char smem[];
    const int tid = threadIdx.x;
    const int wid = tid >> 5, lid = tid & 31;
    const int g = lid >> 2, ti = lid & 3;     // mma fragment coords
    const int mbase = wid * 16;               // warp owns rows [mbase, mbase+16)
    const int grow = mbase + (lid >> 1);      // gather row for this thread
    const int grp4 = (lid & 1) * 4;           // gather group base

    int*      labels_s = (int*)(smem + OFF_LABEL);
    float*    b1s   = (float*)(smem + OFF_BIAS1);
    float*    b2ps  = (float*)(smem + OFF_BIAS2);
    uint2*    B1p   = (uint2*)(smem + OFF_B1);
    uint2*    B2p   = (uint2*)(smem + OFF_B2);
    __half*   B1h   = (__half*)(smem + OFF_B1);
    __half*   B2h   = (__half*)(smem + OFF_B2);
    uint32_t* A1u   = (uint32_t*)(smem + OFF_A1);
    float*    stg   = (float*)(smem + OFF_STG + wid * 8192);   // warp-private 16x128

    // ================= PROLOGUE =================
    // stage W2 (f16 k-major) in A1 region; WpT (f16, [n][j]) in STG region
    {
        __half* W2sh  = (__half*)(smem + OFF_A1);
        __half* WpTsh = (__half*)(smem + OFF_STG);
        for (int idx = tid; idx < EDIM * EDIM; idx += NTHR) {
            int r = idx >> 7, j = idx & 127;
            W2sh[(r * W2S_STRIDE + (j >> 1)) * 2 + (j & 1)] = __float2half(__ldg(W2 + idx));
            int jj = idx >> 7, n = idx & 127;
            WpTsh[(n * WPT_STRIDE + (jj >> 1)) * 2 + (jj & 1)] = __float2half(__ldg(Wp + idx));
        }
        for (int idx = tid; idx < K1DIM * EDIM; idx += NTHR) {
            int k = idx >> 7, n = idx & 127;
            B1h[pair_half_idx(k, n)] = __float2half(__ldg(W1 + idx));
        }
        // zero B1 pad words (kp 36..39): s=4, w=1
        for (int i = tid; i < 512; i += NTHR) {
            int t4 = i >> 7, n = i & 127;
            ((uint32_t*)B1p)[(4 * PAIR_S + t4 * PAIR_TI + n) * 2 + 1] = 0;
        }
        if (tid < EDIM) b1s[tid] = __ldg(b1 + tid);
    }
    __syncthreads();

    // fold W2p = W2 @ Wp_top via tensor cores -> B2 steps 0..7
    {
        const uint32_t* W2s  = (const uint32_t*)(smem + OFF_A1);
        const uint32_t* WpTs = (const uint32_t*)(smem + OFF_STG);
        float facc[16][4];
        #pragma unroll
        for (int j = 0; j < 16; j++)
            #pragma unroll
            for (int u = 0; u < 4; u++) facc[j][u] = 0.f;
        #pragma unroll
        for (int s = 0; s < 8; s++) {
            int jp0 = 8 * s + ti;
            uint32_t a0 = W2s[(mbase + g) * W2S_STRIDE + jp0];
            uint32_t a1 = W2s[(mbase + g + 8) * W2S_STRIDE + jp0];
            uint32_t a2 = W2s[(mbase + g) * W2S_STRIDE + jp0 + 4];
            uint32_t a3 = W2s[(mbase + g + 8) * W2S_STRIDE + jp0 + 4];
            #pragma unroll
            for (int j = 0; j < 16; j++) {
                uint32_t b0 = WpTs[(8 * j + g) * WPT_STRIDE + jp0];
                uint32_t b1v = WpTs[(8 * j + g) * WPT_STRIDE + jp0 + 4];
                mma_f16(facc[j], a0, a1, a2, a3, b0, b1v);
            }
        }
        #pragma unroll
        for (int j = 0; j < 16; j++) {
            int n0 = 8 * j + 2 * ti;
            B2h[pair_half_idx(mbase + g, n0)]     = __float2half(facc[j][0]);
            B2h[pair_half_idx(mbase + g, n0 + 1)] = __float2half(facc[j][1]);
            B2h[pair_half_idx(mbase + g + 8, n0)]     = __float2half(facc[j][2]);
            B2h[pair_half_idx(mbase + g + 8, n0 + 1)] = __float2half(facc[j][3]);
        }
        if (tid < EDIM) {
            float ba = 0.f;
            #pragma unroll 8
            for (int j = 0; j < EDIM; j++) ba += __ldg(b2 + j) * __ldg(Wp + (size_t)j * EDIM + tid);
            b2ps[tid] = ba;
        }
    }
    __syncthreads();

    // fourier scratch in A1 region: scr[d][c], c<31, rows padded to 32
    {
        float* scr = (float*)(smem + OFF_A1);
        for (int t = tid; t < 960; t += NTHR) {
            int d = t / 15, i = t - d * 15;
            float coordf = (float)d * (float)(3.14 / 64.0);
            float fr = coordf * (float)(1 << i);
            scr[d * 32 + i]      = (float)sin((double)fr);
            scr[d * 32 + 15 + i] = (float)cos((double)fr);
            if (i == 0) scr[d * 32 + 30] = coordf;
        }
    }
    __syncthreads();

    // table rows -> B2 steps 8..11 (one-hot block): B2aug[128+d][n] = bias2p[n] + fourier(d)@Wp_bot
    {
        const float* scr = (const float*)(smem + OFF_A1);
        int n = tid & 127, dh = tid >> 7;
        float wpc[31];
        #pragma unroll
        for (int c = 0; c < 31; c++) wpc[c] = __ldg(Wp + (size_t)(EDIM + c) * EDIM + n);
        float bb = b2ps[n];
        #pragma unroll 4
        for (int u = 0; u < 32; u++) {
            int d = dh + 2 * u;
            float acc = bb;
            #pragma unroll
            for (int c = 0; c < 31; c++) acc += scr[d * 32 + c] * wpc[c];
            B2h[pair_half_idx(128 + d, n)] = __float2half(acc);
        }
    }
    __syncthreads();

    // zero A1 K-pad words (kp 36..39), both buffers
    uint32_t* A1w0 = A1u + mbase * A1_STRIDE;
    uint32_t* A1w1 = A1u + (A1_BUF_BYTES / 4) + mbase * A1_STRIDE;
    for (int i = lid; i < 64; i += 32) {
        A1w0[(i >> 2) * A1_STRIDE + 36 + (i & 3)] = 0;
        A1w1[(i >> 2) * A1_STRIDE + 36 + (i & 3)] = 0;
    }

    uint32_t* Gdst0 = A1w0 + (lid >> 1) * A1_STRIDE + (lid & 1) * 18;
    uint32_t* Gdst1 = A1w1 + (lid >> 1) * A1_STRIDE + (lid & 1) * 18;

    // first tile gather (buffer 0)
    {
        int m0p = blockIdx.x * TILE_M;
        int draw = __ldg(label + m0p + grow);
        int dcl = draw < 0 ? 0 : (draw > 63 ? 63 : draw);
        if ((lid & 1) == 0) {
            labels_s[grow] = draw;
            if (out_label) out_label[m0p + grow] = (float)draw;
        }
        const float* rec = cost + (size_t)((m0p + grow) >> 2) * (GGRP * DDISP);
        float gv[36];
        #pragma unroll
        for (int gi = 0; gi < 4; gi++) {
            const float* src = rec + (grp4 + gi) * DDISP;
            #pragma unroll
            for (int c = 0; c < 9; c++) {
                int ix = dcl - 4 + c;
                ix = ix < 0 ? 0 : (ix > 63 ? 63 : ix);
                gv[gi * 9 + c] = __ldg(src + ix);
            }
        }
        #pragma unroll
        for (int w = 0; w < 18; w++) Gdst0[w] = pack_h2(gv[2 * w], gv[2 * w + 1]);
    }
    __syncwarp();

    // ================= MAIN LOOP =================
    int cb = 0;
    for (int tile = blockIdx.x; tile < NTILES; tile += GRID_X) {
        const int m0 = tile * TILE_M;
        const int nxt = tile + GRID_X;
        const bool hn = nxt < NTILES;
        uint32_t* A1w = cb ? A1w1 : A1w0;
        uint32_t* Gdst = cb ? Gdst0 : Gdst1;

        int draw = 0;
        if (hn) draw = __ldg(label + nxt * TILE_M + grow);

        // d values for this tile's one-hot rows (this warp, rows g and g+8)
        int dg0 = labels_s[cb * TILE_M + mbase + g];
        int dg1 = labels_s[cb * TILE_M + mbase + g + 8];
        dg0 = dg0 < 0 ? 0 : (dg0 > 63 ? 63 : dg0);
        dg1 = dg1 < 0 ? 0 : (dg1 > 63 ? 63 : dg1);

        // ---- GEMM1: m16 x n128, K=80 (5 k16 steps) ----
        float acc1[16][4];
        #pragma unroll
        for (int j = 0; j < 16; j++)
            #pragma unroll
            for (int u = 0; u < 4; u++) acc1[j][u] = 0.f;

        #pragma unroll
        for (int s = 0; s < 5; s++) {
            int kp0 = 8 * s + ti;
            uint32_t a0 = A1w[g * A1_STRIDE + kp0];
            uint32_t a1 = A1w[(g + 8) * A1_STRIDE + kp0];
            uint32_t a2 = A1w[g * A1_STRIDE + kp0 + 4];
            uint32_t a3 = A1w[(g + 8) * A1_STRIDE + kp0 + 4];
            const uint2* bp = B1p + s * PAIR_S + ti * PAIR_TI + g;
            #pragma unroll
            for (int j = 0; j < 16; j++) {
                uint2 b = bp[8 * j];
                mma_f16(acc1[j], a0, a1, a2, a3, b.x, b.y);
            }
        }

        // ---- gelu(x+b1), repack as GEMM2 A-frags ----
        uint32_t ha[8][4];
        #pragma unroll
        for (int s = 0; s < 8; s++) {
            int j0 = 2 * s, j1 = 2 * s + 1;
            float2 bb0 = *(const float2*)(b1s + 8 * j0 + 2 * ti);
            float2 bb1 = *(const float2*)(b1s + 8 * j1 + 2 * ti);
            ha[s][0] = pack_h2(gelu_fast(acc1[j0][0] + bb0.x), gelu_fast(acc1[j0][1] + bb0.y));
            ha[s][1] = pack_h2(gelu_fast(acc1[j0][2] + bb0.x), gelu_fast(acc1[j0][3] + bb0.y));
            ha[s][2] = pack_h2(gelu_fast(acc1[j1][0] + bb1.x), gelu_fast(acc1[j1][1] + bb1.y));
            ha[s][3] = pack_h2(gelu_fast(acc1[j1][2] + bb1.x), gelu_fast(acc1[j1][3] + bb1.y));
        }

        // ---- issue next-tile gather loads ----
        float gv[36];
        if (hn) {
            int dcl = draw < 0 ? 0 : (draw > 63 ? 63 : draw);
            const float* rec = cost + (size_t)((nxt * TILE_M + grow) >> 2) * (GGRP * DDISP);
            #pragma unroll
            for (int gi = 0; gi < 4; gi++) {
                const float* src = rec + (grp4 + gi) * DDISP;
                #pragma unroll
                for (int c = 0; c < 9; c++) {
                    int ix = dcl - 4 + c;
                    ix = ix < 0 ? 0 : (ix > 63 ? 63 : ix);
                    gv[gi * 9 + c] = __ldg(src + ix);
                }
            }
        }

        // ---- GEMM2: K=192 (8 ha steps + 4 one-hot steps) ----
        float acc2[16][4];
        #pragma unroll
        for (int j = 0; j < 16; j++)
            #pragma unroll
            for (int u = 0; u < 4; u++) acc2[j][u] = 0.f;

        #pragma unroll
        for (int s = 0; s < 8; s++) {
            const uint2* bp = B2p + s * PAIR_S + ti * PAIR_TI + g;
            #pragma unroll
            for (int j = 0; j < 16; j++) {
                uint2 b = bp[8 * j];
                mma_f16(acc2[j], ha[s][0], ha[s][1], ha[s][2], ha[s][3], b.x, b.y);
            }
        }
        #pragma unroll
        for (int s = 0; s < 4; s++) {
            int kb = 16 * s + 2 * ti;                 // dd-space base for a0/a1
            uint32_t a0 = oh2(dg0, kb);
            uint32_t a1 = oh2(dg1, kb);
            uint32_t a2 = oh2(dg0, kb + 8);
            uint32_t a3 = oh2(dg1, kb + 8);
            const uint2* bp = B2p + (8 + s) * PAIR_S + ti * PAIR_TI + g;
            #pragma unroll
            for (int j = 0; j < 16; j++) {
                uint2 b = bp[8 * j];
                mma_f16(acc2[j], a0, a1, a2, a3, b.x, b.y);
            }
        }

        // ---- staged epilogue: STS (swizzled) -> LDS.128 -> dense STG.128 ----
        {
            const int swz = 8 * (g & 3);
            #pragma unroll
            for (int j = 0; j < 16; j++) {
                int col = 8 * j + 2 * ti;
                *(float2*)(stg + g * 128 + (col ^ swz)) = make_float2(acc2[j][0], acc2[j][1]);
                *(float2*)(stg + (g + 8) * 128 + (col ^ swz)) = make_float2(acc2[j][2], acc2[j][3]);
            }
            __syncwarp();
            float* obase = out_embed + (size_t)(m0 + mbase) * EDIM;
            #pragma unroll
            for (int r = 0; r < 16; r++) {
                float4 v = *(const float4*)(stg + r * 128 + ((lid * 4) ^ (8 * (r & 3))));
                *(float4*)(obase + r * EDIM + lid * 4) = v;
            }
        }

        // ---- commit next-tile gather + labels (warp-private) ----
        if (hn) {
            #pragma unroll
            for (int w = 0; w < 18; w++) Gdst[w] = pack_h2(gv[2 * w], gv[2 * w + 1]);
            if ((lid & 1) == 0) {
                labels_s[(cb ^ 1) * TILE_M + grow] = draw;
                if (out_label) out_label[nxt * TILE_M + grow] = (float)draw;
            }
        }
        __syncwarp();
        cb ^= 1;
    }
}

// ---------------- launch ----------------
extern "C" void kernel_launch(void* const* d_in, const int* in_sizes, int n_in,
                              void* d_out, int out_size) {
    const float* cost  = (const float*)d_in[0];
    const int*   label = (const int*)d_in[1];
    // d_in[2] = context (unused: layers=[] passthrough)
    const float* W1 = (const float*)d_in[3];
    const float* b1 = (const float*)d_in[4];
    const float* W2 = (const float*)d_in[5];
    const float* b2 = (const float*)d_in[6];
    const float* Wp = (const float*)d_in[7];

    float* out = (float*)d_out;
    float* out_label = (out_size >= TOT_ELEMS) ? (out + EMB_ELEMS) : nullptr;

    cudaFuncSetAttribute(propagation_kernel,
                         cudaFuncAttributeMaxDynamicSharedMemorySize, SMEM_TOTAL);

    propagation_kernel<<<GRID_X, NTHR, SMEM_TOTAL>>>(cost, label, W1, b1, W2, b2, Wp,
                                                     out, out_label);
}